// round 1
// baseline (speedup 1.0000x reference)
#include <cuda_runtime.h>
#include <math.h>

#define N_RAYS    131072
#define N_SAMPLES 128
#define BIG_DIST  1e10f
#define EPS       1e-10f

// One warp per ray. Lane l in chunk k owns sample s = 32*k + l.
// Exclusive cumprod of (1 - alpha + eps) via 4 sequential warp
// multiplicative scans with carried product T.
__global__ void __launch_bounds__(256, 8)
nerf_render_kernel(const float4* __restrict__ raw,     // [R, S] float4
                   const float*  __restrict__ z_vals,  // [R, S]
                   const float*  __restrict__ rays_d,  // [R, 3]
                   float* __restrict__ out)
{
    const unsigned FULL = 0xFFFFFFFFu;
    int gwarp = (blockIdx.x * blockDim.x + threadIdx.x) >> 5;
    int lane  = threadIdx.x & 31;
    if (gwarp >= N_RAYS) return;
    const int r = gwarp;

    // |rays_d| — 3 broadcast loads per warp
    float dx = __ldg(&rays_d[3 * r + 0]);
    float dy = __ldg(&rays_d[3 * r + 1]);
    float dz = __ldg(&rays_d[3 * r + 2]);
    float dnorm = sqrtf(dx * dx + dy * dy + dz * dz);

    const float4* rawr = raw    + (size_t)r * N_SAMPLES;
    const float*  zr   = z_vals + (size_t)r * N_SAMPLES;

    float* out_rgb   = out;                                        // [R,3]
    float* out_disp  = out + (size_t)3 * N_RAYS;                   // [R]
    float* out_acc   = out + (size_t)4 * N_RAYS;                   // [R]
    float* out_w     = out + (size_t)5 * N_RAYS;                   // [R,S]
    float* out_depth = out + (size_t)5 * N_RAYS
                           + (size_t)N_RAYS * N_SAMPLES;           // [R]

    float T = 1.0f;            // carried transmittance product
    float a_r = 0.f, a_g = 0.f, a_b = 0.f;   // rgb accumulators
    float a_acc = 0.f, a_depth = 0.f;

    #pragma unroll
    for (int k = 0; k < 4; ++k) {
        const int s = 32 * k + lane;

        float z = zr[s];
        float dist;
        if (s == N_SAMPLES - 1) dist = BIG_DIST;
        else                    dist = zr[s + 1] - z;
        dist *= dnorm;

        float4 rv = rawr[s];
        float sigma = fmaxf(rv.w, 0.0f);
        float alpha = 1.0f - expf(-sigma * dist);

        // multiplicative inclusive scan of v = 1 - alpha + eps
        float v = 1.0f - alpha + EPS;
        float inc = v;
        #pragma unroll
        for (int d = 1; d < 32; d <<= 1) {
            float t = __shfl_up_sync(FULL, inc, d);
            if (lane >= d) inc *= t;
        }
        float exc = __shfl_up_sync(FULL, inc, 1);
        if (lane == 0) exc = 1.0f;

        float trans  = T * exc;
        float weight = alpha * trans;

        // carry for next chunk
        T *= __shfl_sync(FULL, inc, 31);

        // write weight (coalesced)
        out_w[(size_t)r * N_SAMPLES + s] = weight;

        // accumulate
        float cr = 1.0f / (1.0f + expf(-rv.x));
        float cg = 1.0f / (1.0f + expf(-rv.y));
        float cb = 1.0f / (1.0f + expf(-rv.z));
        a_r     += weight * cr;
        a_g     += weight * cg;
        a_b     += weight * cb;
        a_acc   += weight;
        a_depth += weight * z;
    }

    // butterfly reduce 5 accumulators across the warp
    #pragma unroll
    for (int off = 16; off > 0; off >>= 1) {
        a_r     += __shfl_xor_sync(FULL, a_r,     off);
        a_g     += __shfl_xor_sync(FULL, a_g,     off);
        a_b     += __shfl_xor_sync(FULL, a_b,     off);
        a_acc   += __shfl_xor_sync(FULL, a_acc,   off);
        a_depth += __shfl_xor_sync(FULL, a_depth, off);
    }

    if (lane == 0) {
        out_rgb[3 * r + 0] = a_r;
        out_rgb[3 * r + 1] = a_g;
        out_rgb[3 * r + 2] = a_b;
        out_acc[r]   = a_acc;
        out_depth[r] = a_depth;
        out_disp[r]  = 1.0f / fmaxf(EPS, a_depth / a_acc);
    }
}

extern "C" void kernel_launch(void* const* d_in, const int* in_sizes, int n_in,
                              void* d_out, int out_size)
{
    const float4* raw    = (const float4*)d_in[0];   // [R, S, 4] -> float4 per sample
    const float*  z_vals = (const float*)d_in[1];    // [R, S]
    const float*  rays_d = (const float*)d_in[2];    // [R, 3]
    float* out = (float*)d_out;

    const int warps_per_block = 256 / 32;            // 8 rays per block
    const int blocks = (N_RAYS + warps_per_block - 1) / warps_per_block;
    nerf_render_kernel<<<blocks, 256>>>(raw, z_vals, rays_d, out);
}

// round 2
// speedup vs baseline: 1.1939x; 1.1939x over previous
#include <cuda_runtime.h>
#include <math.h>

#define N_RAYS    131072
#define N_SAMPLES 128
#define BIG_DIST  1e10f
#define EPS       1e-10f

// One warp per ray. Lane l owns 4 CONTIGUOUS samples s = 4l .. 4l+3.
// Exclusive cumprod: in-lane serial products + ONE 5-level warp scan.
// Fast-math transcendentals (__expf) — precision budget is 1e-3, we're at 6e-7.
__global__ void __launch_bounds__(256, 8)
nerf_render_kernel(const float4* __restrict__ raw,     // [R, S] float4
                   const float4* __restrict__ z4,      // [R, S/4] float4
                   const float*  __restrict__ rays_d,  // [R, 3]
                   float* __restrict__ out)
{
    const unsigned FULL = 0xFFFFFFFFu;
    int gwarp = (blockIdx.x * blockDim.x + threadIdx.x) >> 5;
    int lane  = threadIdx.x & 31;
    const int r = gwarp;

    float dx = __ldg(&rays_d[3 * r + 0]);
    float dy = __ldg(&rays_d[3 * r + 1]);
    float dz = __ldg(&rays_d[3 * r + 2]);
    float dnorm = sqrtf(dx * dx + dy * dy + dz * dz);

    // z: lane l loads z[4l..4l+3] as one float4 (perfect 128B/warp)
    float4 z = z4[(size_t)r * 32 + lane];
    // z[4l+4] = next lane's z.x (lane 31: unused, dist = BIG)
    float z_next = __shfl_down_sync(FULL, z.x, 1);

    float zv[4] = { z.x, z.y, z.z, z.w };
    float dist[4];
    dist[0] = (z.y - z.x) * dnorm;
    dist[1] = (z.z - z.y) * dnorm;
    dist[2] = (z.w - z.z) * dnorm;
    dist[3] = (lane == 31) ? (BIG_DIST * dnorm) : ((z_next - z.w) * dnorm);

    // raw: 4 float4 loads, stride 64B across lanes (full line utilization)
    const float4* rawr = raw + (size_t)r * N_SAMPLES + 4 * lane;
    float4 rv[4];
    rv[0] = rawr[0]; rv[1] = rawr[1]; rv[2] = rawr[2]; rv[3] = rawr[3];

    // alpha_i, v_i = 1 - alpha_i + eps
    float alpha[4], v[4];
    #pragma unroll
    for (int i = 0; i < 4; ++i) {
        float sigma = fmaxf(rv[i].w, 0.0f);
        alpha[i] = 1.0f - __expf(-sigma * dist[i]);
        v[i] = 1.0f - alpha[i] + EPS;
    }

    // in-lane serial products
    float p01   = v[0] * v[1];
    float p012  = p01 * v[2];
    float p     = p012 * v[3];

    // warp inclusive scan (multiplicative) of p — 5 dependent shuffles
    float inc = p;
    #pragma unroll
    for (int d = 1; d < 32; d <<= 1) {
        float t = __shfl_up_sync(FULL, inc, d);
        if (lane >= d) inc *= t;
    }
    // exclusive prefix for this lane's first sample
    float E = __shfl_up_sync(FULL, inc, 1);
    if (lane == 0) E = 1.0f;

    // per-sample exclusive transmittance and weights
    float w[4];
    w[0] = alpha[0] * E;
    w[1] = alpha[1] * (E * v[0]);
    w[2] = alpha[2] * (E * p01);
    w[3] = alpha[3] * (E * p012);

    // weights store: one float4 per lane (perfect coalescing)
    float* out_w = out + (size_t)5 * N_RAYS;
    ((float4*)(out_w + (size_t)r * N_SAMPLES))[lane] =
        make_float4(w[0], w[1], w[2], w[3]);

    // sigmoid(rgb) and accumulate
    float a_r = 0.f, a_g = 0.f, a_b = 0.f, a_acc = 0.f, a_depth = 0.f;
    #pragma unroll
    for (int i = 0; i < 4; ++i) {
        float cr = __frcp_rn(1.0f + __expf(-rv[i].x));
        float cg = __frcp_rn(1.0f + __expf(-rv[i].y));
        float cb = __frcp_rn(1.0f + __expf(-rv[i].z));
        a_r     += w[i] * cr;
        a_g     += w[i] * cg;
        a_b     += w[i] * cb;
        a_acc   += w[i];
        a_depth += w[i] * zv[i];
    }

    // butterfly reduce 5 accumulators (independent shuffles pipeline)
    #pragma unroll
    for (int off = 16; off > 0; off >>= 1) {
        a_r     += __shfl_xor_sync(FULL, a_r,     off);
        a_g     += __shfl_xor_sync(FULL, a_g,     off);
        a_b     += __shfl_xor_sync(FULL, a_b,     off);
        a_acc   += __shfl_xor_sync(FULL, a_acc,   off);
        a_depth += __shfl_xor_sync(FULL, a_depth, off);
    }

    if (lane == 0) {
        float* out_rgb   = out;
        float* out_disp  = out + (size_t)3 * N_RAYS;
        float* out_acc   = out + (size_t)4 * N_RAYS;
        float* out_depth = out + (size_t)5 * N_RAYS
                               + (size_t)N_RAYS * N_SAMPLES;
        out_rgb[3 * r + 0] = a_r;
        out_rgb[3 * r + 1] = a_g;
        out_rgb[3 * r + 2] = a_b;
        out_acc[r]   = a_acc;
        out_depth[r] = a_depth;
        out_disp[r]  = 1.0f / fmaxf(EPS, a_depth / a_acc);
    }
}

extern "C" void kernel_launch(void* const* d_in, const int* in_sizes, int n_in,
                              void* d_out, int out_size)
{
    const float4* raw    = (const float4*)d_in[0];   // [R, S, 4]
    const float4* z_vals = (const float4*)d_in[1];   // [R, S] viewed as float4
    const float*  rays_d = (const float*)d_in[2];    // [R, 3]
    float* out = (float*)d_out;

    const int warps_per_block = 256 / 32;            // 8 rays per block
    const int blocks = N_RAYS / warps_per_block;     // 16384
    nerf_render_kernel<<<blocks, 256>>>(raw, z_vals, rays_d, out);
}

// round 4
// speedup vs baseline: 1.2652x; 1.0597x over previous
#include <cuda_runtime.h>
#include <math.h>

#define N_RAYS    131072
#define N_SAMPLES 128
#define BIG_DIST  1e10f
#define EPS       1e-10f

__device__ __forceinline__ float fast_rcp(float x) {
    float y;
    asm("rcp.approx.f32 %0, %1;" : "=f"(y) : "f"(x));
    return y;
}

// One warp per ray. Chunk k in [0,4), lane l owns sample s = 32k + l.
// All global accesses coalesced. All shuffles UNCONDITIONAL (convergent),
// results selected afterwards.
__global__ void __launch_bounds__(256)
nerf_render_kernel(const float4* __restrict__ raw,     // [R, S] float4
                   const float*  __restrict__ z_vals,  // [R, S]
                   const float*  __restrict__ rays_d,  // [R, 3]
                   float* __restrict__ out)
{
    const unsigned FULL = 0xFFFFFFFFu;
    int gwarp = (blockIdx.x * blockDim.x + threadIdx.x) >> 5;
    int lane  = threadIdx.x & 31;
    const int r = gwarp;

    float dx = __ldg(&rays_d[3 * r + 0]);
    float dy = __ldg(&rays_d[3 * r + 1]);
    float dz = __ldg(&rays_d[3 * r + 2]);
    float dnorm = sqrtf(dx * dx + dy * dy + dz * dz);

    const float4* rawr = raw    + (size_t)r * N_SAMPLES;
    const float*  zr   = z_vals + (size_t)r * N_SAMPLES;

    // ---- coalesced loads: chunk k, lane l -> sample 32k+l ----
    float zc[4];
    float4 rv[4];
    #pragma unroll
    for (int k = 0; k < 4; ++k) {
        zc[k] = zr[32 * k + lane];      // 128B per instr, 1 line
        rv[k] = rawr[32 * k + lane];    // 512B per instr, 4 lines, fully used
    }

    // ---- dists (all shuffles convergent) ----
    // znext within chunk:
    float zn0 = __shfl_down_sync(FULL, zc[0], 1);
    float zn1 = __shfl_down_sync(FULL, zc[1], 1);
    float zn2 = __shfl_down_sync(FULL, zc[2], 1);
    float zn3 = __shfl_down_sync(FULL, zc[3], 1);
    // first element of next chunk (broadcast, convergent):
    float h1 = __shfl_sync(FULL, zc[1], 0);
    float h2 = __shfl_sync(FULL, zc[2], 0);
    float h3 = __shfl_sync(FULL, zc[3], 0);
    if (lane == 31) { zn0 = h1; zn1 = h2; zn2 = h3; }

    float dist[4];
    dist[0] = (zn0 - zc[0]) * dnorm;
    dist[1] = (zn1 - zc[1]) * dnorm;
    dist[2] = (zn2 - zc[2]) * dnorm;
    dist[3] = (lane == 31) ? (BIG_DIST * dnorm) : ((zn3 - zc[3]) * dnorm);

    float alpha[4], v[4];
    #pragma unroll
    for (int k = 0; k < 4; ++k) {
        float sigma = fmaxf(rv[k].w, 0.0f);
        alpha[k] = 1.0f - __expf(-sigma * dist[k]);
        v[k] = 1.0f - alpha[k] + EPS;
    }

    // ---- 4 parallel multiplicative inclusive scans (levels pipeline) ----
    float inc0 = v[0], inc1 = v[1], inc2 = v[2], inc3 = v[3];
    #pragma unroll
    for (int d = 1; d < 32; d <<= 1) {
        float t0 = __shfl_up_sync(FULL, inc0, d);
        float t1 = __shfl_up_sync(FULL, inc1, d);
        float t2 = __shfl_up_sync(FULL, inc2, d);
        float t3 = __shfl_up_sync(FULL, inc3, d);
        if (lane >= d) { inc0 *= t0; inc1 *= t1; inc2 *= t2; inc3 *= t3; }
    }

    // chunk totals (independent broadcasts, convergent)
    float P0 = __shfl_sync(FULL, inc0, 31);
    float P1 = __shfl_sync(FULL, inc1, 31);
    float P2 = __shfl_sync(FULL, inc2, 31);
    float T1 = P0;
    float T2 = P0 * P1;
    float T3 = T2 * P2;

    // exclusive prefixes within chunks (convergent)
    float e0 = __shfl_up_sync(FULL, inc0, 1);
    float e1 = __shfl_up_sync(FULL, inc1, 1);
    float e2 = __shfl_up_sync(FULL, inc2, 1);
    float e3 = __shfl_up_sync(FULL, inc3, 1);
    if (lane == 0) { e0 = 1.0f; e1 = 1.0f; e2 = 1.0f; e3 = 1.0f; }

    float w[4];
    w[0] = alpha[0] * e0;
    w[1] = alpha[1] * (T1 * e1);
    w[2] = alpha[2] * (T2 * e2);
    w[3] = alpha[3] * (T3 * e3);

    // ---- coalesced weight stores ----
    float* out_w = out + (size_t)5 * N_RAYS + (size_t)r * N_SAMPLES;
    #pragma unroll
    for (int k = 0; k < 4; ++k)
        out_w[32 * k + lane] = w[k];

    // ---- sigmoid(rgb) with fast rcp, accumulate ----
    float a_r = 0.f, a_g = 0.f, a_b = 0.f, a_acc = 0.f, a_depth = 0.f;
    #pragma unroll
    for (int k = 0; k < 4; ++k) {
        float cr = fast_rcp(1.0f + __expf(-rv[k].x));
        float cg = fast_rcp(1.0f + __expf(-rv[k].y));
        float cb = fast_rcp(1.0f + __expf(-rv[k].z));
        a_r     += w[k] * cr;
        a_g     += w[k] * cg;
        a_b     += w[k] * cb;
        a_acc   += w[k];
        a_depth += w[k] * zc[k];
    }

    // ---- butterfly reduction (5 independent chains pipeline) ----
    #pragma unroll
    for (int off = 16; off > 0; off >>= 1) {
        a_r     += __shfl_xor_sync(FULL, a_r,     off);
        a_g     += __shfl_xor_sync(FULL, a_g,     off);
        a_b     += __shfl_xor_sync(FULL, a_b,     off);
        a_acc   += __shfl_xor_sync(FULL, a_acc,   off);
        a_depth += __shfl_xor_sync(FULL, a_depth, off);
    }

    if (lane == 0) {
        float* out_rgb   = out;
        float* out_disp  = out + (size_t)3 * N_RAYS;
        float* out_acc   = out + (size_t)4 * N_RAYS;
        float* out_depth = out + (size_t)5 * N_RAYS
                               + (size_t)N_RAYS * N_SAMPLES;
        out_rgb[3 * r + 0] = a_r;
        out_rgb[3 * r + 1] = a_g;
        out_rgb[3 * r + 2] = a_b;
        out_acc[r]   = a_acc;
        out_depth[r] = a_depth;
        out_disp[r]  = fast_rcp(fmaxf(EPS, a_depth * fast_rcp(a_acc)));
    }
}

extern "C" void kernel_launch(void* const* d_in, const int* in_sizes, int n_in,
                              void* d_out, int out_size)
{
    const float4* raw    = (const float4*)d_in[0];   // [R, S, 4]
    const float*  z_vals = (const float*)d_in[1];    // [R, S]
    const float*  rays_d = (const float*)d_in[2];    // [R, 3]
    float* out = (float*)d_out;

    const int warps_per_block = 256 / 32;            // 8 rays per block
    const int blocks = N_RAYS / warps_per_block;     // 16384
    nerf_render_kernel<<<blocks, 256>>>(raw, z_vals, rays_d, out);
}

// round 6
// speedup vs baseline: 1.3185x; 1.0421x over previous
#include <cuda_runtime.h>
#include <math.h>

#define N_RAYS    131072
#define N_SAMPLES 128
#define BIG_DIST  1e10f
#define EPS       1e-10f

__device__ __forceinline__ float fast_rcp(float x) {
    float y; asm("rcp.approx.f32 %0, %1;" : "=f"(y) : "f"(x)); return y;
}
__device__ __forceinline__ float fast_ex2(float x) {
    float y; asm("ex2.approx.ftz.f32 %0, %1;" : "=f"(y) : "f"(x)); return y;
}
__device__ __forceinline__ float fast_tanh(float x) {
    float y; asm("tanh.approx.f32 %0, %1;" : "=f"(y) : "f"(x)); return y;
}
__device__ __forceinline__ float sigmoid_fast(float x) {
    return fmaf(fast_tanh(0.5f * x), 0.5f, 0.5f);
}

// One warp per ray. Chunk k in [0,4), lane l owns sample s = 32k + l.
// Coalesced streams with .cs eviction hints; ex2/tanh approx math;
// pipelined butterfly for final reductions (redux.f32 unsupported on sm_103).
__global__ void __launch_bounds__(256)
nerf_render_kernel(const float4* __restrict__ raw,     // [R, S] float4
                   const float*  __restrict__ z_vals,  // [R, S]
                   const float*  __restrict__ rays_d,  // [R, 3]
                   float* __restrict__ out)
{
    const unsigned FULL = 0xFFFFFFFFu;
    int gwarp = (blockIdx.x * blockDim.x + threadIdx.x) >> 5;
    int lane  = threadIdx.x & 31;
    const int r = gwarp;

    float dx = __ldg(&rays_d[3 * r + 0]);
    float dy = __ldg(&rays_d[3 * r + 1]);
    float dz = __ldg(&rays_d[3 * r + 2]);
    float dnorm = sqrtf(dx * dx + dy * dy + dz * dz);
    // fold |d| and log2(e): exp(-s*dz*|d|) = ex2(s*dz*c)
    const float c = -dnorm * 1.4426950408889634f;

    const float4* rawr = raw    + (size_t)r * N_SAMPLES;
    const float*  zr   = z_vals + (size_t)r * N_SAMPLES;

    // ---- coalesced loads (streaming hint on the big raw stream) ----
    float zc[4];
    float4 rv[4];
    #pragma unroll
    for (int k = 0; k < 4; ++k) {
        zc[k] = __ldcs(&zr[32 * k + lane]);
        rv[k] = __ldcs(&rawr[32 * k + lane]);
    }

    // ---- dz (all shuffles convergent) ----
    float zn0 = __shfl_down_sync(FULL, zc[0], 1);
    float zn1 = __shfl_down_sync(FULL, zc[1], 1);
    float zn2 = __shfl_down_sync(FULL, zc[2], 1);
    float zn3 = __shfl_down_sync(FULL, zc[3], 1);
    float h1 = __shfl_sync(FULL, zc[1], 0);
    float h2 = __shfl_sync(FULL, zc[2], 0);
    float h3 = __shfl_sync(FULL, zc[3], 0);
    if (lane == 31) { zn0 = h1; zn1 = h2; zn2 = h3; }

    float dzv[4];
    dzv[0] = zn0 - zc[0];
    dzv[1] = zn1 - zc[1];
    dzv[2] = zn2 - zc[2];
    dzv[3] = (lane == 31) ? BIG_DIST : (zn3 - zc[3]);

    // ---- alpha & v: e = ex2(sigma*dz*c); alpha = 1-e; v = e+eps ----
    float alpha[4], v[4];
    #pragma unroll
    for (int k = 0; k < 4; ++k) {
        float sigma = fmaxf(rv[k].w, 0.0f);
        float e = fast_ex2(sigma * dzv[k] * c);
        alpha[k] = 1.0f - e;
        v[k] = e + EPS;
    }

    // ---- 4 parallel multiplicative inclusive scans ----
    float inc0 = v[0], inc1 = v[1], inc2 = v[2], inc3 = v[3];
    #pragma unroll
    for (int d = 1; d < 32; d <<= 1) {
        float t0 = __shfl_up_sync(FULL, inc0, d);
        float t1 = __shfl_up_sync(FULL, inc1, d);
        float t2 = __shfl_up_sync(FULL, inc2, d);
        float t3 = __shfl_up_sync(FULL, inc3, d);
        if (lane >= d) { inc0 *= t0; inc1 *= t1; inc2 *= t2; inc3 *= t3; }
    }

    float P0 = __shfl_sync(FULL, inc0, 31);
    float P1 = __shfl_sync(FULL, inc1, 31);
    float P2 = __shfl_sync(FULL, inc2, 31);
    float T1 = P0;
    float T2 = P0 * P1;
    float T3 = T2 * P2;

    float e0 = __shfl_up_sync(FULL, inc0, 1);
    float e1 = __shfl_up_sync(FULL, inc1, 1);
    float e2 = __shfl_up_sync(FULL, inc2, 1);
    float e3 = __shfl_up_sync(FULL, inc3, 1);
    if (lane == 0) { e0 = 1.0f; e1 = 1.0f; e2 = 1.0f; e3 = 1.0f; }

    float w[4];
    w[0] = alpha[0] * e0;
    w[1] = alpha[1] * (T1 * e1);
    w[2] = alpha[2] * (T2 * e2);
    w[3] = alpha[3] * (T3 * e3);

    // ---- coalesced streaming weight stores ----
    float* out_w = out + (size_t)5 * N_RAYS + (size_t)r * N_SAMPLES;
    #pragma unroll
    for (int k = 0; k < 4; ++k)
        __stcs(&out_w[32 * k + lane], w[k]);

    // ---- sigmoid(rgb) via tanh.approx, accumulate ----
    float a_r = 0.f, a_g = 0.f, a_b = 0.f, a_acc = 0.f, a_depth = 0.f;
    #pragma unroll
    for (int k = 0; k < 4; ++k) {
        a_r     = fmaf(w[k], sigmoid_fast(rv[k].x), a_r);
        a_g     = fmaf(w[k], sigmoid_fast(rv[k].y), a_g);
        a_b     = fmaf(w[k], sigmoid_fast(rv[k].z), a_b);
        a_acc  += w[k];
        a_depth = fmaf(w[k], zc[k], a_depth);
    }

    // ---- butterfly reduction (5 independent chains pipeline) ----
    #pragma unroll
    for (int off = 16; off > 0; off >>= 1) {
        a_r     += __shfl_xor_sync(FULL, a_r,     off);
        a_g     += __shfl_xor_sync(FULL, a_g,     off);
        a_b     += __shfl_xor_sync(FULL, a_b,     off);
        a_acc   += __shfl_xor_sync(FULL, a_acc,   off);
        a_depth += __shfl_xor_sync(FULL, a_depth, off);
    }

    if (lane == 0) {
        float* out_rgb   = out;
        float* out_disp  = out + (size_t)3 * N_RAYS;
        float* out_acc   = out + (size_t)4 * N_RAYS;
        float* out_depth = out + (size_t)5 * N_RAYS
                               + (size_t)N_RAYS * N_SAMPLES;
        out_rgb[3 * r + 0] = a_r;
        out_rgb[3 * r + 1] = a_g;
        out_rgb[3 * r + 2] = a_b;
        out_acc[r]   = a_acc;
        out_depth[r] = a_depth;
        out_disp[r]  = fast_rcp(fmaxf(EPS, a_depth * fast_rcp(a_acc)));
    }
}

extern "C" void kernel_launch(void* const* d_in, const int* in_sizes, int n_in,
                              void* d_out, int out_size)
{
    const float4* raw    = (const float4*)d_in[0];   // [R, S, 4]
    const float*  z_vals = (const float*)d_in[1];    // [R, S]
    const float*  rays_d = (const float*)d_in[2];    // [R, 3]
    float* out = (float*)d_out;

    const int warps_per_block = 256 / 32;            // 8 rays per block
    const int blocks = N_RAYS / warps_per_block;     // 16384
    nerf_render_kernel<<<blocks, 256>>>(raw, z_vals, rays_d, out);
}